// round 2
// baseline (speedup 1.0000x reference)
#include <cuda_runtime.h>
#include <math.h>

#define BB 4
#define NN 4096
#define CC 256
#define CK 32

// Scratch (device globals — no allocation allowed)
__device__ float d_f[BB * NN * CK];
__device__ float d_g[BB * NN * CK];
__device__ float d_h[(size_t)BB * NN * CC];
__device__ float d_o[(size_t)BB * NN * CC];

typedef unsigned long long ull;

__device__ __forceinline__ ull pack2(float lo, float hi) {
    ull r; asm("mov.b64 %0, {%1, %2};" : "=l"(r) : "f"(lo), "f"(hi)); return r;
}
__device__ __forceinline__ void unpack2(ull v, float& lo, float& hi) {
    asm("mov.b64 {%0, %1}, %2;" : "=f"(lo), "=f"(hi) : "l"(v));
}
__device__ __forceinline__ ull ffma2(ull a, ull b, ull c) {
    ull d; asm("fma.rn.f32x2 %0, %1, %2, %3;" : "=l"(d) : "l"(a), "l"(b), "l"(c)); return d;
}
__device__ __forceinline__ ull fmul2(ull a, ull b) {
    ull d; asm("mul.rn.f32x2 %0, %1, %2;" : "=l"(d) : "l"(a), "l"(b)); return d;
}

// ---------------------------------------------------------------------------
// f/g projection: [16384,256] @ ([256,32]||[256,32]) -> d_f, d_g
// Block: 256 threads, 64 rows x 64 cols (f cols 0-31, g cols 32-63)
// ---------------------------------------------------------------------------
__global__ __launch_bounds__(256) void k_proj_fg(
    const float* __restrict__ x,
    const float* __restrict__ Wf, const float* __restrict__ bf,
    const float* __restrict__ Wg, const float* __restrict__ bg)
{
    __shared__ __align__(16) float sA[64 * 32];
    __shared__ __align__(16) float sW[32 * 64];
    const int tid = threadIdx.x;
    const int row0 = blockIdx.x * 64;
    const int ty = tid >> 4, tx = tid & 15;

    ull acc[4][2] = {};

    for (int k0 = 0; k0 < 256; k0 += 32) {
        __syncthreads();
#pragma unroll
        for (int i = 0; i < 2; i++) {
            int e4 = tid * 2 + i;
            int r = e4 >> 3, kk = (e4 & 7) << 2;
            *(float4*)&sA[r * 32 + kk] =
                *(const float4*)&x[(size_t)(row0 + r) * 256 + k0 + kk];
        }
#pragma unroll
        for (int i = 0; i < 8; i++) {
            int e = tid + 256 * i;
            int k = e >> 6, c = e & 63;
            float w = (c < 32) ? Wf[(k0 + k) * 32 + c] : Wg[(k0 + k) * 32 + (c - 32)];
            sW[k * 64 + c] = w;
        }
        __syncthreads();
#pragma unroll
        for (int k = 0; k < 32; ++k) {
            ulonglong2 wv = *(const ulonglong2*)&sW[k * 64 + tx * 4];
#pragma unroll
            for (int i = 0; i < 4; ++i) {
                float a = sA[(ty * 4 + i) * 32 + k];
                ull a2 = pack2(a, a);
                acc[i][0] = ffma2(a2, wv.x, acc[i][0]);
                acc[i][1] = ffma2(a2, wv.y, acc[i][1]);
            }
        }
    }

    const int cbase = tx * 4;
#pragma unroll
    for (int i = 0; i < 4; ++i) {
        float v0, v1, v2, v3;
        unpack2(acc[i][0], v0, v1);
        unpack2(acc[i][1], v2, v3);
        int row = row0 + ty * 4 + i;
        if (cbase < 32) {
            float4 o4 = make_float4(v0 + bf[cbase], v1 + bf[cbase + 1],
                                    v2 + bf[cbase + 2], v3 + bf[cbase + 3]);
            *(float4*)&d_f[row * CK + cbase] = o4;
        } else {
            int cg = cbase - 32;
            float4 o4 = make_float4(v0 + bg[cg], v1 + bg[cg + 1],
                                    v2 + bg[cg + 2], v3 + bg[cg + 3]);
            *(float4*)&d_g[row * CK + cg] = o4;
        }
    }
}

// ---------------------------------------------------------------------------
// Generic 256-col GEMM: out = A @ W + bias (+ res).  mode 0: A=x -> d_h.
// mode 1: A=d_o, res=x -> external out.
// ---------------------------------------------------------------------------
__global__ __launch_bounds__(256) void k_gemm256(
    const float* __restrict__ Aext, const float* __restrict__ W,
    const float* __restrict__ bias, const float* __restrict__ res,
    float* __restrict__ outext, int mode)
{
    const float* A = (mode == 0) ? Aext : d_o;
    float* out = (mode == 0) ? d_h : outext;

    __shared__ __align__(16) float sA[64 * 32];
    __shared__ __align__(16) float sW[32 * 64];
    const int tid = threadIdx.x;
    const int row0 = blockIdx.x * 64;
    const int n0 = blockIdx.y * 64;
    const int ty = tid >> 4, tx = tid & 15;

    ull acc[4][2] = {};

    for (int k0 = 0; k0 < 256; k0 += 32) {
        __syncthreads();
#pragma unroll
        for (int i = 0; i < 2; i++) {
            int e4 = tid * 2 + i;
            int r = e4 >> 3, kk = (e4 & 7) << 2;
            *(float4*)&sA[r * 32 + kk] =
                *(const float4*)&A[(size_t)(row0 + r) * 256 + k0 + kk];
        }
#pragma unroll
        for (int i = 0; i < 8; i++) {
            int e = tid + 256 * i;
            int k = e >> 6, c = e & 63;
            sW[k * 64 + c] = W[(size_t)(k0 + k) * 256 + n0 + c];
        }
        __syncthreads();
#pragma unroll
        for (int k = 0; k < 32; ++k) {
            ulonglong2 wv = *(const ulonglong2*)&sW[k * 64 + tx * 4];
#pragma unroll
            for (int i = 0; i < 4; ++i) {
                float a = sA[(ty * 4 + i) * 32 + k];
                ull a2 = pack2(a, a);
                acc[i][0] = ffma2(a2, wv.x, acc[i][0]);
                acc[i][1] = ffma2(a2, wv.y, acc[i][1]);
            }
        }
    }

    const int c0 = n0 + tx * 4;
    float4 b4 = *(const float4*)&bias[c0];
#pragma unroll
    for (int i = 0; i < 4; ++i) {
        float v0, v1, v2, v3;
        unpack2(acc[i][0], v0, v1);
        unpack2(acc[i][1], v2, v3);
        int row = row0 + ty * 4 + i;
        v0 += b4.x; v1 += b4.y; v2 += b4.z; v3 += b4.w;
        if (res) {
            float4 r4 = *(const float4*)&res[(size_t)row * 256 + c0];
            v0 += r4.x; v1 += r4.y; v2 += r4.z; v3 += r4.w;
        }
        *(float4*)&out[(size_t)row * 256 + c0] = make_float4(v0, v1, v2, v3);
    }
}

// ---------------------------------------------------------------------------
// Flash attention: per CTA: 64 query rows of one batch.
// s = g f^T (no scale), online softmax, o = beta @ h.
// smem: sg 8K + sfT 8K + sp 16K + sh 16K = 48KB (static, no attribute calls).
// ---------------------------------------------------------------------------
__global__ __launch_bounds__(256) void k_attn()
{
    __shared__ __align__(16) float sg[64 * 32];
    __shared__ __align__(16) float sfT[32 * 64];   // [k][key]
    __shared__ __align__(16) float sp[64 * 64];    // [q][key]
    __shared__ __align__(16) float sh[16 * 256];   // [key-chunk][c]

    const int tid = threadIdx.x;
    const int ty = tid >> 4, tx = tid & 15;
    const int b = blockIdx.y;
    const int q0 = blockIdx.x * 64;

    const float* fptr = d_f + (size_t)b * NN * CK;
    const float* gptr = d_g + (size_t)b * NN * CK;
    const float* hptr = d_h + (size_t)b * NN * CC;

    // load g tile (resident for whole kernel)
#pragma unroll
    for (int i = 0; i < 2; i++) {
        int e4 = tid * 2 + i;
        int r = e4 >> 3, kk = (e4 & 7) << 2;
        *(float4*)&sg[r * 32 + kk] = *(const float4*)&gptr[(q0 + r) * CK + kk];
    }

    const float NEG_INF = __int_as_float(0xff800000);
    float m_i[4] = {NEG_INF, NEG_INF, NEG_INF, NEG_INF};
    float l_i[4] = {0.f, 0.f, 0.f, 0.f};
    ull o2[4][8] = {};

    for (int kt = 0; kt < 64; ++kt) {
        const int k0 = kt * 64;
        __syncthreads();  // prior tile's sfT/sp reads complete
        // load f tile transposed: sfT[k][key] = f[k0+key][k]
#pragma unroll
        for (int i = 0; i < 2; i++) {
            int e4 = tid * 2 + i;
            int r = e4 >> 3, kk = (e4 & 7) << 2;
            float4 v = *(const float4*)&fptr[(k0 + r) * CK + kk];
            sfT[(kk + 0) * 64 + r] = v.x;
            sfT[(kk + 1) * 64 + r] = v.y;
            sfT[(kk + 2) * 64 + r] = v.z;
            sfT[(kk + 3) * 64 + r] = v.w;
        }
        __syncthreads();

        // s tile: 4 q-rows x 4 key-cols per thread
        ull ss2[4][2] = {};
#pragma unroll
        for (int k = 0; k < 32; ++k) {
            ulonglong2 wv = *(const ulonglong2*)&sfT[k * 64 + tx * 4];
#pragma unroll
            for (int i = 0; i < 4; ++i) {
                float a = sg[(ty * 4 + i) * 32 + k];
                ull a2 = pack2(a, a);
                ss2[i][0] = ffma2(a2, wv.x, ss2[i][0]);
                ss2[i][1] = ffma2(a2, wv.y, ss2[i][1]);
            }
        }

        // online softmax update per q-row (row spread across 16-lane tx group)
#pragma unroll
        for (int i = 0; i < 4; ++i) {
            float s0, s1, s2v, s3;
            unpack2(ss2[i][0], s0, s1);
            unpack2(ss2[i][1], s2v, s3);
            float mt = fmaxf(fmaxf(s0, s1), fmaxf(s2v, s3));
#pragma unroll
            for (int off = 8; off; off >>= 1)
                mt = fmaxf(mt, __shfl_xor_sync(0xffffffffu, mt, off));
            float mnew = fmaxf(m_i[i], mt);
            float p0 = __expf(s0 - mnew);
            float p1 = __expf(s1 - mnew);
            float p2v = __expf(s2v - mnew);
            float p3 = __expf(s3 - mnew);
            float ls = (p0 + p1) + (p2v + p3);
#pragma unroll
            for (int off = 8; off; off >>= 1)
                ls += __shfl_xor_sync(0xffffffffu, ls, off);
            float alpha = __expf(m_i[i] - mnew);
            l_i[i] = l_i[i] * alpha + ls;
            m_i[i] = mnew;
            ull a2 = pack2(alpha, alpha);
#pragma unroll
            for (int j = 0; j < 8; ++j) o2[i][j] = fmul2(o2[i][j], a2);
            *(float4*)&sp[(ty * 4 + i) * 64 + tx * 4] = make_float4(p0, p1, p2v, p3);
        }

        // o += p @ h, streaming h in 16-row chunks through smem
        for (int hc = 0; hc < 4; ++hc) {
            __syncthreads();  // sp visible (hc==0) / prior sh reads complete
#pragma unroll
            for (int i = 0; i < 4; ++i) {
                int e4 = tid + 256 * i;
                int r = e4 >> 6, c4 = (e4 & 63) << 2;
                *(float4*)&sh[r * 256 + c4] =
                    *(const float4*)&hptr[(size_t)(k0 + hc * 16 + r) * CC + c4];
            }
            __syncthreads();
#pragma unroll
            for (int kk = 0; kk < 16; ++kk) {
                ull p2[4];
#pragma unroll
                for (int i = 0; i < 4; ++i) {
                    float pv = sp[(ty * 4 + i) * 64 + hc * 16 + kk];
                    p2[i] = pack2(pv, pv);
                }
#pragma unroll
                for (int j = 0; j < 4; ++j) {
                    ulonglong2 hv = *(const ulonglong2*)&sh[kk * 256 + j * 64 + tx * 4];
#pragma unroll
                    for (int i = 0; i < 4; ++i) {
                        o2[i][2 * j]     = ffma2(p2[i], hv.x, o2[i][2 * j]);
                        o2[i][2 * j + 1] = ffma2(p2[i], hv.y, o2[i][2 * j + 1]);
                    }
                }
            }
        }
    }

    // epilogue: o / l -> d_o
    float* optr = d_o + (size_t)b * NN * CC;
#pragma unroll
    for (int i = 0; i < 4; ++i) {
        float inv = 1.0f / l_i[i];
        int row = q0 + ty * 4 + i;
#pragma unroll
        for (int j = 0; j < 4; ++j) {
            float a, bb2, c, d;
            unpack2(o2[i][2 * j], a, bb2);
            unpack2(o2[i][2 * j + 1], c, d);
            *(float4*)&optr[(size_t)row * 256 + j * 64 + tx * 4] =
                make_float4(a * inv, bb2 * inv, c * inv, d * inv);
        }
    }
}

// ---------------------------------------------------------------------------
extern "C" void kernel_launch(void* const* d_in, const int* in_sizes, int n_in,
                              void* d_out, int out_size)
{
    const float* x  = (const float*)d_in[0];
    const float* Wf = (const float*)d_in[1];
    const float* bf = (const float*)d_in[2];
    const float* Wg = (const float*)d_in[3];
    const float* bg = (const float*)d_in[4];
    const float* Wh = (const float*)d_in[5];
    const float* bh = (const float*)d_in[6];
    const float* Wv = (const float*)d_in[7];
    const float* bv = (const float*)d_in[8];
    float* out = (float*)d_out;

    k_proj_fg<<<256, 256>>>(x, Wf, bf, Wg, bg);
    k_gemm256<<<dim3(256, 4), 256>>>(x, Wh, bh, nullptr, nullptr, 0);
    k_attn<<<dim3(64, 4), 256>>>();
    k_gemm256<<<dim3(256, 4), 256>>>(nullptr, Wv, bv, x, out, 1);
}

// round 4
// speedup vs baseline: 3.4803x; 3.4803x over previous
#include <cuda_runtime.h>
#include <cuda_fp16.h>
#include <math.h>
#include <stdint.h>

#define BB 4
#define NN 4096
#define CC 256
#define L2E 1.4426950408889634f

typedef unsigned long long ull;
typedef unsigned int u32;

// ---------------- scratch (device globals; no allocation allowed) ----------
__device__ __half d_f16p[BB * NN * 64];                 // [n][0:32)=f_hi, [32:64)=f_lo
__device__ __half d_g16[BB * NN * 64];                  // [n][0:32)=g_hi, [32:64)=g_lo
__device__ __half d_h16T[(size_t)BB * CC * NN];         // [b][c][n]
__device__ float  d_o[(size_t)BB * NN * CC];            // attention out fp32

// ---------------- f32x2 helpers (projections) -------------------------------
__device__ __forceinline__ ull pack2(float lo, float hi) {
    ull r; asm("mov.b64 %0, {%1, %2};" : "=l"(r) : "f"(lo), "f"(hi)); return r;
}
__device__ __forceinline__ void unpack2(ull v, float& lo, float& hi) {
    asm("mov.b64 {%0, %1}, %2;" : "=f"(lo), "=f"(hi) : "l"(v));
}
__device__ __forceinline__ ull ffma2(ull a, ull b, ull c) {
    ull d; asm("fma.rn.f32x2 %0, %1, %2, %3;" : "=l"(d) : "l"(a), "l"(b), "l"(c)); return d;
}

// ---------------- mma / cp.async helpers -------------------------------------
__device__ __forceinline__ void mma16816(float* c, const u32* a, u32 b0, u32 b1) {
    asm volatile(
        "mma.sync.aligned.m16n8k16.row.col.f32.f16.f16.f32 "
        "{%0,%1,%2,%3}, {%4,%5,%6,%7}, {%8,%9}, {%0,%1,%2,%3};"
        : "+f"(c[0]), "+f"(c[1]), "+f"(c[2]), "+f"(c[3])
        : "r"(a[0]), "r"(a[1]), "r"(a[2]), "r"(a[3]), "r"(b0), "r"(b1));
}
__device__ __forceinline__ u32 smem_u32(const void* p) {
    u32 a;
    asm("{ .reg .u64 t; cvta.to.shared.u64 t, %1; cvt.u32.u64 %0, t; }" : "=r"(a) : "l"(p));
    return a;
}
__device__ __forceinline__ void cpa16(u32 s, const void* g) {
    asm volatile("cp.async.cg.shared.global [%0], [%1], 16;" :: "r"(s), "l"(g));
}
#define CP_COMMIT() asm volatile("cp.async.commit_group;" ::: "memory")
#define CP_WAIT0()  asm volatile("cp.async.wait_group 0;" ::: "memory")
#define CP_WAIT1()  asm volatile("cp.async.wait_group 1;" ::: "memory")

// ---------------------------------------------------------------------------
// f/g projection -> split fp16 hi/lo rows [key][hi32|lo32]
// ---------------------------------------------------------------------------
__global__ __launch_bounds__(256) void k_proj_fg(
    const float* __restrict__ x,
    const float* __restrict__ Wf, const float* __restrict__ bf,
    const float* __restrict__ Wg, const float* __restrict__ bg)
{
    __shared__ __align__(16) float sA[64 * 32];
    __shared__ __align__(16) float sW[32 * 64];
    const int tid = threadIdx.x;
    const int row0 = blockIdx.x * 64;
    const int ty = tid >> 4, tx = tid & 15;
    ull acc[4][2] = {};

    for (int k0 = 0; k0 < 256; k0 += 32) {
        __syncthreads();
#pragma unroll
        for (int i = 0; i < 2; i++) {
            int e4 = tid * 2 + i;
            int r = e4 >> 3, kk = (e4 & 7) << 2;
            *(float4*)&sA[r * 32 + kk] = *(const float4*)&x[(size_t)(row0 + r) * 256 + k0 + kk];
        }
#pragma unroll
        for (int i = 0; i < 8; i++) {
            int e = tid + 256 * i;
            int k = e >> 6, c = e & 63;
            sW[k * 64 + c] = (c < 32) ? Wf[(k0 + k) * 32 + c] : Wg[(k0 + k) * 32 + (c - 32)];
        }
        __syncthreads();
#pragma unroll
        for (int k = 0; k < 32; ++k) {
            ulonglong2 wv = *(const ulonglong2*)&sW[k * 64 + tx * 4];
#pragma unroll
            for (int i = 0; i < 4; ++i) {
                float a = sA[(ty * 4 + i) * 32 + k];
                ull a2 = pack2(a, a);
                acc[i][0] = ffma2(a2, wv.x, acc[i][0]);
                acc[i][1] = ffma2(a2, wv.y, acc[i][1]);
            }
        }
    }

    const int cbase = tx * 4;
#pragma unroll
    for (int i = 0; i < 4; ++i) {
        float v[4];
        unpack2(acc[i][0], v[0], v[1]);
        unpack2(acc[i][1], v[2], v[3]);
        int row = row0 + ty * 4 + i;
        __half hi[4], lo[4];
        if (cbase < 32) {
#pragma unroll
            for (int j = 0; j < 4; ++j) {
                float val = v[j] + bf[cbase + j];
                hi[j] = __float2half_rn(val);
                lo[j] = __float2half_rn(val - __half2float(hi[j]));
            }
            *(uint2*)&d_f16p[(size_t)row * 64 + cbase] = *(uint2*)hi;
            *(uint2*)&d_f16p[(size_t)row * 64 + 32 + cbase] = *(uint2*)lo;
        } else {
            int cg = cbase - 32;
#pragma unroll
            for (int j = 0; j < 4; ++j) {
                float val = v[j] + bg[cg + j];
                hi[j] = __float2half_rn(val);
                lo[j] = __float2half_rn(val - __half2float(hi[j]));
            }
            *(uint2*)&d_g16[(size_t)row * 64 + cg] = *(uint2*)hi;
            *(uint2*)&d_g16[(size_t)row * 64 + 32 + cg] = *(uint2*)lo;
        }
    }
}

// ---------------------------------------------------------------------------
// h projection: h = x @ Wh + bh, stored transposed fp16 [b][c][n]
// ---------------------------------------------------------------------------
__global__ __launch_bounds__(256) void k_hproj(
    const float* __restrict__ x, const float* __restrict__ Wh, const float* __restrict__ bh)
{
    __shared__ __align__(16) float sA[64 * 32];
    __shared__ __align__(16) float sW[32 * 64];
    const int tid = threadIdx.x;
    const int row0 = blockIdx.x * 64;
    const int n0 = blockIdx.y * 64;
    const int ty = tid >> 4, tx = tid & 15;
    ull acc[4][2] = {};

    for (int k0 = 0; k0 < 256; k0 += 32) {
        __syncthreads();
#pragma unroll
        for (int i = 0; i < 2; i++) {
            int e4 = tid * 2 + i;
            int r = e4 >> 3, kk = (e4 & 7) << 2;
            *(float4*)&sA[r * 32 + kk] = *(const float4*)&x[(size_t)(row0 + r) * 256 + k0 + kk];
        }
#pragma unroll
        for (int i = 0; i < 8; i++) {
            int e = tid + 256 * i;
            int k = e >> 6, c = e & 63;
            sW[k * 64 + c] = Wh[(size_t)(k0 + k) * 256 + n0 + c];
        }
        __syncthreads();
#pragma unroll
        for (int k = 0; k < 32; ++k) {
            ulonglong2 wv = *(const ulonglong2*)&sW[k * 64 + tx * 4];
#pragma unroll
            for (int i = 0; i < 4; ++i) {
                float a = sA[(ty * 4 + i) * 32 + k];
                ull a2 = pack2(a, a);
                acc[i][0] = ffma2(a2, wv.x, acc[i][0]);
                acc[i][1] = ffma2(a2, wv.y, acc[i][1]);
            }
        }
    }

    float vv[4][4];
#pragma unroll
    for (int i = 0; i < 4; ++i) {
        unpack2(acc[i][0], vv[i][0], vv[i][1]);
        unpack2(acc[i][1], vv[i][2], vv[i][3]);
    }
    const size_t b = (size_t)(row0 >> 12);
    const int nl = (row0 & 4095) + ty * 4;
#pragma unroll
    for (int j = 0; j < 4; ++j) {
        int c = n0 + tx * 4 + j;
        float bb = bh[c];
        __half2 h01 = __floats2half2_rn(vv[0][j] + bb, vv[1][j] + bb);
        __half2 h23 = __floats2half2_rn(vv[2][j] + bb, vv[3][j] + bb);
        uint2 u; u.x = *(u32*)&h01; u.y = *(u32*)&h23;
        *(uint2*)&d_h16T[b * (size_t)CC * NN + (size_t)c * NN + nl] = u;
    }
}

// ---------------------------------------------------------------------------
// v projection + residual: out = x + d_o @ Wv + bv
// ---------------------------------------------------------------------------
__global__ __launch_bounds__(256) void k_vproj(
    const float* __restrict__ W, const float* __restrict__ bias,
    const float* __restrict__ res, float* __restrict__ out)
{
    __shared__ __align__(16) float sA[64 * 32];
    __shared__ __align__(16) float sW[32 * 64];
    const int tid = threadIdx.x;
    const int row0 = blockIdx.x * 64;
    const int n0 = blockIdx.y * 64;
    const int ty = tid >> 4, tx = tid & 15;
    ull acc[4][2] = {};

    for (int k0 = 0; k0 < 256; k0 += 32) {
        __syncthreads();
#pragma unroll
        for (int i = 0; i < 2; i++) {
            int e4 = tid * 2 + i;
            int r = e4 >> 3, kk = (e4 & 7) << 2;
            *(float4*)&sA[r * 32 + kk] = *(const float4*)&d_o[(size_t)(row0 + r) * 256 + k0 + kk];
        }
#pragma unroll
        for (int i = 0; i < 8; i++) {
            int e = tid + 256 * i;
            int k = e >> 6, c = e & 63;
            sW[k * 64 + c] = W[(size_t)(k0 + k) * 256 + n0 + c];
        }
        __syncthreads();
#pragma unroll
        for (int k = 0; k < 32; ++k) {
            ulonglong2 wv = *(const ulonglong2*)&sW[k * 64 + tx * 4];
#pragma unroll
            for (int i = 0; i < 4; ++i) {
                float a = sA[(ty * 4 + i) * 32 + k];
                ull a2 = pack2(a, a);
                acc[i][0] = ffma2(a2, wv.x, acc[i][0]);
                acc[i][1] = ffma2(a2, wv.y, acc[i][1]);
            }
        }
    }

    const int c0 = n0 + tx * 4;
    float4 b4 = *(const float4*)&bias[c0];
#pragma unroll
    for (int i = 0; i < 4; ++i) {
        float v0, v1, v2, v3;
        unpack2(acc[i][0], v0, v1);
        unpack2(acc[i][1], v2, v3);
        int row = row0 + ty * 4 + i;
        float4 r4 = *(const float4*)&res[(size_t)row * 256 + c0];
        *(float4*)&out[(size_t)row * 256 + c0] =
            make_float4(v0 + b4.x + r4.x, v1 + b4.y + r4.y, v2 + b4.z + r4.z, v3 + b4.w + r4.w);
    }
}

// ---------------------------------------------------------------------------
// HMMA flash attention. CTA = 128 q rows, 256 threads (8 warps x 16 rows).
// Pass A: row max from hi-only S. Pass B: 3-term S, P=exp2 fp16, O += P@H,
// li via ones-MMA.  smem: F 2x18432 + H 2x69632 = 176128 B.
// ---------------------------------------------------------------------------
#define SF_STRIDE 144
#define SH_STRIDE 272
#define SF_BYTES (128 * SF_STRIDE)
#define SH_BYTES (256 * SH_STRIDE)
#define ATTN_SMEM (2 * SF_BYTES + 2 * SH_BYTES)
#define ONES_H2 0x3C003C00u

__global__ __launch_bounds__(256) void k_attn()
{
    extern __shared__ __align__(16) char dsm[];
    char* sFp[2] = { dsm, dsm + SF_BYTES };
    char* sHp[2] = { dsm + 2 * SF_BYTES, dsm + 2 * SF_BYTES + SH_BYTES };
    u32 sFu[2] = { smem_u32(sFp[0]), smem_u32(sFp[1]) };
    u32 sHu[2] = { smem_u32(sHp[0]), smem_u32(sHp[1]) };

    const int tid = threadIdx.x;
    const int w = tid >> 5, lane = tid & 31;
    const int qr = lane >> 2;            // row within m16 group
    const int kq = (lane & 3) << 1;      // 2*(lane%4)
    const int b = blockIdx.y, q0 = blockIdx.x * 128;

    const char* fglob = (const char*)(d_f16p + (size_t)b * NN * 64);
    const char* hglob = (const char*)(d_h16T + (size_t)b * CC * NN);

    // ---- G fragments (K=32: 2 chunks, hi+lo) ----
    u32 Ghi[2][4], Glo[2][4];
    {
        const char* g0 = (const char*)(d_g16 + (size_t)(b * NN + q0 + 16 * w) * 64);
#pragma unroll
        for (int c = 0; c < 2; ++c) {
            int kb = 16 * c + kq;
            Ghi[c][0] = *(const u32*)(g0 + (size_t)qr * 128 + kb * 2);
            Ghi[c][1] = *(const u32*)(g0 + (size_t)(qr + 8) * 128 + kb * 2);
            Ghi[c][2] = *(const u32*)(g0 + (size_t)qr * 128 + (kb + 8) * 2);
            Ghi[c][3] = *(const u32*)(g0 + (size_t)(qr + 8) * 128 + (kb + 8) * 2);
            Glo[c][0] = *(const u32*)(g0 + (size_t)qr * 128 + 64 + kb * 2);
            Glo[c][1] = *(const u32*)(g0 + (size_t)(qr + 8) * 128 + 64 + kb * 2);
            Glo[c][2] = *(const u32*)(g0 + (size_t)qr * 128 + 64 + (kb + 8) * 2);
            Glo[c][3] = *(const u32*)(g0 + (size_t)(qr + 8) * 128 + 64 + (kb + 8) * 2);
        }
    }

    // ================= Pass A: row max (hi-only S) =================
    float mrow0 = -1e30f, mrow1 = -1e30f;

    // preload F tile 0
    {
        const char* gb = fglob;
#pragma unroll
        for (int i = 0; i < 4; i++) {
            int e = tid + 256 * i; int row = e >> 3, q = e & 7;
            cpa16(sFu[0] + row * SF_STRIDE + q * 16, gb + row * 128 + q * 16);
        }
        CP_COMMIT();
    }
#pragma unroll 1
    for (int kt = 0; kt < 32; ++kt) {
        if (kt < 31) {
            const char* gb = fglob + (size_t)(kt + 1) * 16384;
            u32 sb = sFu[(kt + 1) & 1];
#pragma unroll
            for (int i = 0; i < 4; i++) {
                int e = tid + 256 * i; int row = e >> 3, q = e & 7;
                cpa16(sb + row * SF_STRIDE + q * 16, gb + row * 128 + q * 16);
            }
            CP_COMMIT();
            CP_WAIT1();
        } else {
            CP_WAIT0();
        }
        __syncthreads();
        const char* fb = sFp[kt & 1];
#pragma unroll
        for (int j = 0; j < 16; ++j) {
            float c4[4] = {0.f, 0.f, 0.f, 0.f};
            u32 base = (8 * j + qr) * SF_STRIDE;
#pragma unroll
            for (int c = 0; c < 2; ++c) {
                u32 off = base + (16 * c + kq) * 2;
                u32 b0 = *(const u32*)(fb + off);
                u32 b1 = *(const u32*)(fb + off + 16);
                mma16816(c4, Ghi[c], b0, b1);
            }
            mrow0 = fmaxf(mrow0, fmaxf(c4[0], c4[1]));
            mrow1 = fmaxf(mrow1, fmaxf(c4[2], c4[3]));
        }
        __syncthreads();
    }
    // quad reduce (lanes sharing the same rows)
    mrow0 = fmaxf(mrow0, __shfl_xor_sync(0xffffffffu, mrow0, 1));
    mrow0 = fmaxf(mrow0, __shfl_xor_sync(0xffffffffu, mrow0, 2));
    mrow1 = fmaxf(mrow1, __shfl_xor_sync(0xffffffffu, mrow1, 1));
    mrow1 = fmaxf(mrow1, __shfl_xor_sync(0xffffffffu, mrow1, 2));
    const float mL0 = mrow0 * L2E, mL1 = mrow1 * L2E;

    // ================= Pass B =================
    float oa[32][4];
#pragma unroll
    for (int j = 0; j < 32; ++j) { oa[j][0] = oa[j][1] = oa[j][2] = oa[j][3] = 0.f; }
    float lacc[4] = {0.f, 0.f, 0.f, 0.f};

    // preload tile 0 (F + H)
    {
#pragma unroll
        for (int i = 0; i < 4; i++) {
            int e = tid + 256 * i; int row = e >> 3, q = e & 7;
            cpa16(sFu[0] + row * SF_STRIDE + q * 16, fglob + row * 128 + q * 16);
        }
#pragma unroll
        for (int i = 0; i < 16; i++) {
            int e = tid + 256 * i; int row = e >> 4, q = e & 15;
            cpa16(sHu[0] + row * SH_STRIDE + q * 16, hglob + (size_t)row * 8192 + q * 16);
        }
        CP_COMMIT();
    }

#pragma unroll 1
    for (int kt = 0; kt < 32; ++kt) {
        if (kt < 31) {
            u32 sfb = sFu[(kt + 1) & 1], shb = sHu[(kt + 1) & 1];
            const char* gf = fglob + (size_t)(kt + 1) * 16384;
            const char* gh = hglob + (size_t)(kt + 1) * 256;
#pragma unroll
            for (int i = 0; i < 4; i++) {
                int e = tid + 256 * i; int row = e >> 3, q = e & 7;
                cpa16(sfb + row * SF_STRIDE + q * 16, gf + row * 128 + q * 16);
            }
#pragma unroll
            for (int i = 0; i < 16; i++) {
                int e = tid + 256 * i; int row = e >> 4, q = e & 15;
                cpa16(shb + row * SH_STRIDE + q * 16, gh + (size_t)row * 8192 + q * 16);
            }
            CP_COMMIT();
            CP_WAIT1();
        } else {
            CP_WAIT0();
        }
        __syncthreads();

        const char* fb = sFp[kt & 1];
        const char* hb = sHp[kt & 1];

        // ---- S (3-term) + softmax -> P fragments ----
        u32 P[8][4];
#pragma unroll
        for (int kk = 0; kk < 8; ++kk) {
            float cA[4] = {0.f, 0.f, 0.f, 0.f};
            float cB[4] = {0.f, 0.f, 0.f, 0.f};
            u32 baseA = (16 * kk + qr) * SF_STRIDE;
            u32 baseB = baseA + 8 * SF_STRIDE;
#pragma unroll
            for (int c = 0; c < 2; ++c) {
                u32 off = (16 * c + kq) * 2;
                u32 ah0 = *(const u32*)(fb + baseA + off);
                u32 ah1 = *(const u32*)(fb + baseA + off + 16);
                u32 al0 = *(const u32*)(fb + baseA + off + 64);
                u32 al1 = *(const u32*)(fb + baseA + off + 80);
                u32 bh0 = *(const u32*)(fb + baseB + off);
                u32 bh1 = *(const u32*)(fb + baseB + off + 16);
                u32 bl0 = *(const u32*)(fb + baseB + off + 64);
                u32 bl1 = *(const u32*)(fb + baseB + off + 80);
                mma16816(cA, Ghi[c], ah0, ah1);
                mma16816(cB, Ghi[c], bh0, bh1);
                mma16816(cA, Glo[c], ah0, ah1);
                mma16816(cB, Glo[c], bh0, bh1);
                mma16816(cA, Ghi[c], al0, al1);
                mma16816(cB, Ghi[c], bl0, bl1);
            }
            __half2 p;
            p = h2exp2(__floats2half2_rn(fmaf(cA[0], L2E, -mL0), fmaf(cA[1], L2E, -mL0)));
            P[kk][0] = *(u32*)&p;
            p = h2exp2(__floats2half2_rn(fmaf(cA[2], L2E, -mL1), fmaf(cA[3], L2E, -mL1)));
            P[kk][1] = *(u32*)&p;
            p = h2exp2(__floats2half2_rn(fmaf(cB[0], L2E, -mL0), fmaf(cB[1], L2E, -mL0)));
            P[kk][2] = *(u32*)&p;
            p = h2exp2(__floats2half2_rn(fmaf(cB[2], L2E, -mL1), fmaf(cB[3], L2E, -mL1)));
            P[kk][3] = *(u32*)&p;
        }

        // ---- li += P @ ones ----
#pragma unroll
        for (int kk = 0; kk < 8; ++kk)
            mma16816(lacc, P[kk], ONES_H2, ONES_H2);

        // ---- O += P @ H ----
#pragma unroll
        for (int kk = 0; kk < 8; ++kk) {
            u32 koff = (16 * kk + kq) * 2;
#pragma unroll
            for (int j2 = 0; j2 < 32; ++j2) {
                u32 a = (8 * j2 + qr) * SH_STRIDE + koff;
                mma16816(oa[j2], P[kk], *(const u32*)(hb + a), *(const u32*)(hb + a + 16));
            }
        }
        __syncthreads();
    }

    // ---- epilogue: o = O / li ----
    {
        float inv0 = 1.0f / lacc[0];
        float inv1 = 1.0f / lacc[2];
        float* op = d_o + ((size_t)b * NN + q0 + 16 * w) * 256;
#pragma unroll
        for (int j2 = 0; j2 < 32; ++j2) {
            int cc = 8 * j2 + kq;
            *(float2*)(op + (size_t)qr * 256 + cc) =
                make_float2(oa[j2][0] * inv0, oa[j2][1] * inv0);
            *(float2*)(op + (size_t)(qr + 8) * 256 + cc) =
                make_float2(oa[j2][2] * inv1, oa[j2][3] * inv1);
        }
    }
}

// ---------------------------------------------------------------------------
extern "C" void kernel_launch(void* const* d_in, const int* in_sizes, int n_in,
                              void* d_out, int out_size)
{
    const float* x  = (const float*)d_in[0];
    const float* Wf = (const float*)d_in[1];
    const float* bf = (const float*)d_in[2];
    const float* Wg = (const float*)d_in[3];
    const float* bg = (const float*)d_in[4];
    const float* Wh = (const float*)d_in[5];
    const float* bh = (const float*)d_in[6];
    const float* Wv = (const float*)d_in[7];
    const float* bv = (const float*)d_in[8];
    float* out = (float*)d_out;

    cudaFuncSetAttribute(k_attn, cudaFuncAttributeMaxDynamicSharedMemorySize, ATTN_SMEM);

    k_proj_fg<<<256, 256>>>(x, Wf, bf, Wg, bg);
    k_hproj<<<dim3(256, 4), 256>>>(x, Wh, bh);
    k_attn<<<dim3(32, 4), 256, ATTN_SMEM>>>();
    k_vproj<<<dim3(256, 4), 256>>>(Wv, bv, x, out);
}

// round 5
// speedup vs baseline: 4.0826x; 1.1731x over previous
#include <cuda_runtime.h>
#include <cuda_fp16.h>
#include <math.h>
#include <stdint.h>

#define BB 4
#define NN 4096
#define CC 256
#define L2E 1.4426950408889634f

typedef unsigned long long ull;
typedef unsigned int u32;

// ---------------- scratch (device globals; no allocation allowed) ----------
__device__ __half d_f16p[BB * NN * 64];                 // [n][0:32)=f_hi, [32:64)=f_lo
__device__ __half d_g16[BB * NN * 64];                  // [n][0:32)=g_hi, [32:64)=g_lo
__device__ __half d_h16T[(size_t)BB * CC * NN];         // [b][c][n]
__device__ float  d_o[(size_t)BB * NN * CC];            // attention out fp32

// ---------------- mma / cp.async helpers -------------------------------------
__device__ __forceinline__ void mma16816(float* c, const u32* a, u32 b0, u32 b1) {
    asm volatile(
        "mma.sync.aligned.m16n8k16.row.col.f32.f16.f16.f32 "
        "{%0,%1,%2,%3}, {%4,%5,%6,%7}, {%8,%9}, {%0,%1,%2,%3};"
        : "+f"(c[0]), "+f"(c[1]), "+f"(c[2]), "+f"(c[3])
        : "r"(a[0]), "r"(a[1]), "r"(a[2]), "r"(a[3]), "r"(b0), "r"(b1));
}
__device__ __forceinline__ u32 smem_u32(const void* p) {
    u32 a;
    asm("{ .reg .u64 t; cvta.to.shared.u64 t, %1; cvt.u32.u64 %0, t; }" : "=r"(a) : "l"(p));
    return a;
}
__device__ __forceinline__ void cpa16(u32 s, const void* g) {
    asm volatile("cp.async.cg.shared.global [%0], [%1], 16;" :: "r"(s), "l"(g));
}
#define CP_COMMIT() asm volatile("cp.async.commit_group;" ::: "memory")
#define CP_WAIT0()  asm volatile("cp.async.wait_group 0;" ::: "memory")
#define CP_WAIT1()  asm volatile("cp.async.wait_group 1;" ::: "memory")

__device__ __forceinline__ u32 f2h2u(float a, float b) {
    __half2 h = __floats2half2_rn(a, b);
    return *(u32*)&h;
}

// ===========================================================================
// Fused f/g/h projection, HMMA 3-term.  CTA = 64 rows, 320 threads.
// Warps 0-7: h cols w*32..w*32+31 (to d_h16T transposed fp16).
// Warp 8: f (hi+lo), warp 9: g (hi+lo).
// ===========================================================================
#define SA_STRIDE 40            // floats per sA row (160B, 16B-aligned)
#define SW_STRIDE 36            // halves per sW row (72B)
#define FGH_NCOL 320
#define FGH_SMEM (20480 + 2 * (FGH_NCOL * SW_STRIDE * 2))   // 66560

__global__ __launch_bounds__(320) void k_fgh(
    const float* __restrict__ x,
    const float* __restrict__ Wh, const float* __restrict__ bh,
    const float* __restrict__ Wf, const float* __restrict__ bf,
    const float* __restrict__ Wg, const float* __restrict__ bg)
{
    extern __shared__ __align__(16) char sm[];
    float* sA[2] = { (float*)sm, (float*)(sm + 10240) };
    __half* sWhi = (__half*)(sm + 20480);
    __half* sWlo = (__half*)(sm + 20480 + FGH_NCOL * SW_STRIDE * 2);
    u32 sAu[2] = { smem_u32(sA[0]), smem_u32(sA[1]) };

    const int tid = threadIdx.x, w = tid >> 5, lane = tid & 31;
    const int qr = lane >> 2, kq2 = (lane & 3) << 1;
    const int row0 = blockIdx.x * 64;
    const char* xrow = (const char*)(x + (size_t)row0 * 256);

    float acc[4][4][4] = {};

    // preload A stage 0
    if (tid < 256) {
#pragma unroll
        for (int i = 0; i < 2; i++) {
            int e = tid * 2 + i; int r = e >> 3, s = e & 7;
            cpa16(sAu[0] + r * 160 + s * 16, xrow + (size_t)r * 1024 + s * 16);
        }
    }
    CP_COMMIT();

    for (int s = 0; s < 8; s++) {
        const int k0 = s * 32;
        __syncthreads();                       // prior mma done with sW & sA[(s+1)&1]
        if (s < 7) {
            if (tid < 256) {
#pragma unroll
                for (int i = 0; i < 2; i++) {
                    int e = tid * 2 + i; int r = e >> 3, seg = e & 7;
                    cpa16(sAu[(s + 1) & 1] + r * 160 + seg * 16,
                          xrow + (size_t)r * 1024 + (k0 + 32) * 4 + seg * 16);
                }
            }
        }
        CP_COMMIT();
        // convert W chunk -> sWhi/sWlo  (thread t = output col)
        {
            const float* wp; int stride;
            if (tid < 256)      { wp = Wh + tid;         stride = 256; }
            else if (tid < 288) { wp = Wf + (tid - 256); stride = 32; }
            else                { wp = Wg + (tid - 288); stride = 32; }
#pragma unroll
            for (int k = 0; k < 32; k++) {
                float v = wp[(size_t)(k0 + k) * stride];
                __half hi = __float2half_rn(v);
                sWhi[tid * SW_STRIDE + k] = hi;
                sWlo[tid * SW_STRIDE + k] = __float2half_rn(v - __half2float(hi));
            }
        }
        if (s < 7) { CP_WAIT1(); } else { CP_WAIT0(); }
        __syncthreads();

        const float* sa = sA[s & 1];
#pragma unroll
        for (int kc = 0; kc < 2; kc++) {
            u32 AH[4][4], AL[4][4];
#pragma unroll
            for (int rg = 0; rg < 4; rg++) {
                const float* base = sa + (rg * 16 + qr) * SA_STRIDE + kc * 16 + kq2;
                float2 v0 = *(const float2*)(base);
                float2 v1 = *(const float2*)(base + 8 * SA_STRIDE);
                float2 v2 = *(const float2*)(base + 8);
                float2 v3 = *(const float2*)(base + 8 * SA_STRIDE + 8);
                __half2 h;
                h = __floats2half2_rn(v0.x, v0.y); AH[rg][0] = *(u32*)&h;
                float2 r0 = __half22float2(h);
                h = __floats2half2_rn(v0.x - r0.x, v0.y - r0.y); AL[rg][0] = *(u32*)&h;
                h = __floats2half2_rn(v1.x, v1.y); AH[rg][1] = *(u32*)&h;
                float2 r1 = __half22float2(h);
                h = __floats2half2_rn(v1.x - r1.x, v1.y - r1.y); AL[rg][1] = *(u32*)&h;
                h = __floats2half2_rn(v2.x, v2.y); AH[rg][2] = *(u32*)&h;
                float2 r2 = __half22float2(h);
                h = __floats2half2_rn(v2.x - r2.x, v2.y - r2.y); AL[rg][2] = *(u32*)&h;
                h = __floats2half2_rn(v3.x, v3.y); AH[rg][3] = *(u32*)&h;
                float2 r3 = __half22float2(h);
                h = __floats2half2_rn(v3.x - r3.x, v3.y - r3.y); AL[rg][3] = *(u32*)&h;
            }
#pragma unroll
            for (int nt = 0; nt < 4; nt++) {
                const __half* bp  = sWhi + (w * 32 + nt * 8 + qr) * SW_STRIDE + kc * 16 + kq2;
                const __half* bpl = sWlo + (w * 32 + nt * 8 + qr) * SW_STRIDE + kc * 16 + kq2;
                u32 bh0 = *(const u32*)bp,  bh1 = *(const u32*)(bp + 8);
                u32 bl0 = *(const u32*)bpl, bl1 = *(const u32*)(bpl + 8);
#pragma unroll
                for (int rg = 0; rg < 4; rg++) {
                    mma16816(acc[rg][nt], AH[rg], bh0, bh1);
                    mma16816(acc[rg][nt], AL[rg], bh0, bh1);
                    mma16816(acc[rg][nt], AH[rg], bl0, bl1);
                }
            }
        }
    }
    __syncthreads();   // loop done; reuse smem for output staging

    if (w < 8) {
        // --- h warps: stage [32 c][64 n] fp16, then coalesced store transposed ---
        __half* reg = (__half*)(sm + w * 4096);
#pragma unroll
        for (int nt = 0; nt < 4; nt++) {
            int cl = nt * 8 + kq2;
            float b0 = bh[w * 32 + cl], b1 = bh[w * 32 + cl + 1];
#pragma unroll
            for (int rg = 0; rg < 4; rg++) {
                int r = rg * 16 + qr;
                __half2 p0 = __floats2half2_rn(acc[rg][nt][0] + b0, acc[rg][nt][1] + b1);
                __half2 p1 = __floats2half2_rn(acc[rg][nt][2] + b0, acc[rg][nt][3] + b1);
                reg[cl * 64 + r]           = __low2half(p0);
                reg[(cl + 1) * 64 + r]     = __high2half(p0);
                reg[cl * 64 + r + 8]       = __low2half(p1);
                reg[(cl + 1) * 64 + r + 8] = __high2half(p1);
            }
        }
        __syncwarp();
        const size_t b = (size_t)(row0 >> 12);
        const int nl = row0 & 4095;
        __half* dstb = d_h16T + b * (size_t)CC * NN;
#pragma unroll
        for (int i = 0; i < 8; i++) {
            int u = i * 32 + lane;
            int cl = u >> 3, seg = u & 7;
            *(uint4*)(dstb + (size_t)(w * 32 + cl) * NN + nl + seg * 8) =
                *(const uint4*)(reg + cl * 64 + seg * 8);
        }
    } else {
        // --- f/g warps: stage [64 n][32 hi | 32 lo] fp16 ---
        __half* reg = (__half*)(sm + 32768 + (w - 8) * 8192);
        const float* bias = (w == 8) ? bf : bg;
#pragma unroll
        for (int nt = 0; nt < 4; nt++) {
            int cl = nt * 8 + kq2;
            float b0 = bias[cl], b1 = bias[cl + 1];
#pragma unroll
            for (int rg = 0; rg < 4; rg++) {
#pragma unroll
                for (int half = 0; half < 2; half++) {
                    int r = rg * 16 + qr + half * 8;
                    float v0 = acc[rg][nt][half * 2] + b0;
                    float v1 = acc[rg][nt][half * 2 + 1] + b1;
                    __half h0 = __float2half_rn(v0);
                    __half h1 = __float2half_rn(v1);
                    reg[r * 64 + cl] = h0;
                    reg[r * 64 + cl + 1] = h1;
                    reg[r * 64 + 32 + cl] = __float2half_rn(v0 - __half2float(h0));
                    reg[r * 64 + 32 + cl + 1] = __float2half_rn(v1 - __half2float(h1));
                }
            }
        }
        __syncwarp();
        __half* dst = ((w == 8) ? d_f16p : d_g16) + (size_t)row0 * 64;
#pragma unroll
        for (int i = 0; i < 16; i++) {
            int u = i * 32 + lane;
            int r = u >> 3, seg = u & 7;
            *(uint4*)(dst + (size_t)r * 64 + seg * 8) = *(const uint4*)(reg + r * 64 + seg * 8);
        }
    }
}

// ===========================================================================
// v projection + residual, HMMA 3-term: out = x + d_o @ Wv + bv.
// CTA = 64 rows, 256 threads, warp w -> cols w*32..
// ===========================================================================
#define VP_SMEM (20480 + 2 * (256 * SW_STRIDE * 2))     // 57344

__global__ __launch_bounds__(256) void k_vproj(
    const float* __restrict__ Wv, const float* __restrict__ bv,
    const float* __restrict__ x, float* __restrict__ out)
{
    extern __shared__ __align__(16) char sm[];
    float* sA[2] = { (float*)sm, (float*)(sm + 10240) };
    __half* sWhi = (__half*)(sm + 20480);
    __half* sWlo = (__half*)(sm + 20480 + 256 * SW_STRIDE * 2);
    u32 sAu[2] = { smem_u32(sA[0]), smem_u32(sA[1]) };

    const int tid = threadIdx.x, w = tid >> 5, lane = tid & 31;
    const int qr = lane >> 2, kq2 = (lane & 3) << 1;
    const int row0 = blockIdx.x * 64;
    const char* arow = (const char*)(d_o + (size_t)row0 * 256);

    float acc[4][4][4] = {};

#pragma unroll
    for (int i = 0; i < 2; i++) {
        int e = tid * 2 + i; int r = e >> 3, s = e & 7;
        cpa16(sAu[0] + r * 160 + s * 16, arow + (size_t)r * 1024 + s * 16);
    }
    CP_COMMIT();

    for (int s = 0; s < 8; s++) {
        const int k0 = s * 32;
        __syncthreads();
        if (s < 7) {
#pragma unroll
            for (int i = 0; i < 2; i++) {
                int e = tid * 2 + i; int r = e >> 3, seg = e & 7;
                cpa16(sAu[(s + 1) & 1] + r * 160 + seg * 16,
                      arow + (size_t)r * 1024 + (k0 + 32) * 4 + seg * 16);
            }
        }
        CP_COMMIT();
        {
#pragma unroll
            for (int k = 0; k < 32; k++) {
                float v = Wv[(size_t)(k0 + k) * 256 + tid];
                __half hi = __float2half_rn(v);
                sWhi[tid * SW_STRIDE + k] = hi;
                sWlo[tid * SW_STRIDE + k] = __float2half_rn(v - __half2float(hi));
            }
        }
        if (s < 7) { CP_WAIT1(); } else { CP_WAIT0(); }
        __syncthreads();

        const float* sa = sA[s & 1];
#pragma unroll
        for (int kc = 0; kc < 2; kc++) {
            u32 AH[4][4], AL[4][4];
#pragma unroll
            for (int rg = 0; rg < 4; rg++) {
                const float* base = sa + (rg * 16 + qr) * SA_STRIDE + kc * 16 + kq2;
                float2 v0 = *(const float2*)(base);
                float2 v1 = *(const float2*)(base + 8 * SA_STRIDE);
                float2 v2 = *(const float2*)(base + 8);
                float2 v3 = *(const float2*)(base + 8 * SA_STRIDE + 8);
                __half2 h;
                h = __floats2half2_rn(v0.x, v0.y); AH[rg][0] = *(u32*)&h;
                float2 r0 = __half22float2(h);
                h = __floats2half2_rn(v0.x - r0.x, v0.y - r0.y); AL[rg][0] = *(u32*)&h;
                h = __floats2half2_rn(v1.x, v1.y); AH[rg][1] = *(u32*)&h;
                float2 r1 = __half22float2(h);
                h = __floats2half2_rn(v1.x - r1.x, v1.y - r1.y); AL[rg][1] = *(u32*)&h;
                h = __floats2half2_rn(v2.x, v2.y); AH[rg][2] = *(u32*)&h;
                float2 r2 = __half22float2(h);
                h = __floats2half2_rn(v2.x - r2.x, v2.y - r2.y); AL[rg][2] = *(u32*)&h;
                h = __floats2half2_rn(v3.x, v3.y); AH[rg][3] = *(u32*)&h;
                float2 r3 = __half22float2(h);
                h = __floats2half2_rn(v3.x - r3.x, v3.y - r3.y); AL[rg][3] = *(u32*)&h;
            }
#pragma unroll
            for (int nt = 0; nt < 4; nt++) {
                const __half* bp  = sWhi + (w * 32 + nt * 8 + qr) * SW_STRIDE + kc * 16 + kq2;
                const __half* bpl = sWlo + (w * 32 + nt * 8 + qr) * SW_STRIDE + kc * 16 + kq2;
                u32 bh0 = *(const u32*)bp,  bh1 = *(const u32*)(bp + 8);
                u32 bl0 = *(const u32*)bpl, bl1 = *(const u32*)(bpl + 8);
#pragma unroll
                for (int rg = 0; rg < 4; rg++) {
                    mma16816(acc[rg][nt], AH[rg], bh0, bh1);
                    mma16816(acc[rg][nt], AL[rg], bh0, bh1);
                    mma16816(acc[rg][nt], AH[rg], bl0, bl1);
                }
            }
        }
    }

    // epilogue: out = acc + bv + x  (direct fp32 stores)
#pragma unroll
    for (int nt = 0; nt < 4; nt++) {
        int c = w * 32 + nt * 8 + kq2;
        float b0 = bv[c], b1 = bv[c + 1];
#pragma unroll
        for (int rg = 0; rg < 4; rg++) {
#pragma unroll
            for (int half = 0; half < 2; half++) {
                int r = row0 + rg * 16 + qr + half * 8;
                float2 xr = *(const float2*)&x[(size_t)r * 256 + c];
                float2 o;
                o.x = acc[rg][nt][half * 2] + b0 + xr.x;
                o.y = acc[rg][nt][half * 2 + 1] + b1 + xr.y;
                *(float2*)&out[(size_t)r * 256 + c] = o;
            }
        }
    }
}

// ===========================================================================
// HMMA flash attention (per-kk fused S->P->O to cut register pressure).
// CTA = 128 q rows, 256 threads (8 warps x 16 rows).
// ===========================================================================
#define SF_STRIDE 144
#define SH_STRIDE 272
#define SF_BYTES (128 * SF_STRIDE)
#define SH_BYTES (256 * SH_STRIDE)
#define ATTN_SMEM (2 * SF_BYTES + 2 * SH_BYTES)
#define ONES_H2 0x3C003C00u

__global__ __launch_bounds__(256) void k_attn()
{
    extern __shared__ __align__(16) char dsm[];
    char* sFp[2] = { dsm, dsm + SF_BYTES };
    char* sHp[2] = { dsm + 2 * SF_BYTES, dsm + 2 * SF_BYTES + SH_BYTES };
    u32 sFu[2] = { smem_u32(sFp[0]), smem_u32(sFp[1]) };
    u32 sHu[2] = { smem_u32(sHp[0]), smem_u32(sHp[1]) };

    const int tid = threadIdx.x;
    const int w = tid >> 5, lane = tid & 31;
    const int qr = lane >> 2;
    const int kq = (lane & 3) << 1;
    const int b = blockIdx.y, q0 = blockIdx.x * 128;

    const char* fglob = (const char*)(d_f16p + (size_t)b * NN * 64);
    const char* hglob = (const char*)(d_h16T + (size_t)b * CC * NN);

    u32 Ghi[2][4], Glo[2][4];
    {
        const char* g0 = (const char*)(d_g16 + (size_t)(b * NN + q0 + 16 * w) * 64);
#pragma unroll
        for (int c = 0; c < 2; ++c) {
            int kb = 16 * c + kq;
            Ghi[c][0] = *(const u32*)(g0 + (size_t)qr * 128 + kb * 2);
            Ghi[c][1] = *(const u32*)(g0 + (size_t)(qr + 8) * 128 + kb * 2);
            Ghi[c][2] = *(const u32*)(g0 + (size_t)qr * 128 + (kb + 8) * 2);
            Ghi[c][3] = *(const u32*)(g0 + (size_t)(qr + 8) * 128 + (kb + 8) * 2);
            Glo[c][0] = *(const u32*)(g0 + (size_t)qr * 128 + 64 + kb * 2);
            Glo[c][1] = *(const u32*)(g0 + (size_t)(qr + 8) * 128 + 64 + kb * 2);
            Glo[c][2] = *(const u32*)(g0 + (size_t)qr * 128 + 64 + (kb + 8) * 2);
            Glo[c][3] = *(const u32*)(g0 + (size_t)(qr + 8) * 128 + 64 + (kb + 8) * 2);
        }
    }

    // ================= Pass A: row max (hi-only S) =================
    float mrow0 = -1e30f, mrow1 = -1e30f;
    {
#pragma unroll
        for (int i = 0; i < 4; i++) {
            int e = tid + 256 * i; int row = e >> 3, q = e & 7;
            cpa16(sFu[0] + row * SF_STRIDE + q * 16, fglob + row * 128 + q * 16);
        }
        CP_COMMIT();
    }
#pragma unroll 1
    for (int kt = 0; kt < 32; ++kt) {
        if (kt < 31) {
            const char* gb = fglob + (size_t)(kt + 1) * 16384;
            u32 sb = sFu[(kt + 1) & 1];
#pragma unroll
            for (int i = 0; i < 4; i++) {
                int e = tid + 256 * i; int row = e >> 3, q = e & 7;
                cpa16(sb + row * SF_STRIDE + q * 16, gb + row * 128 + q * 16);
            }
            CP_COMMIT();
            CP_WAIT1();
        } else {
            CP_WAIT0();
        }
        __syncthreads();
        const char* fb = sFp[kt & 1];
#pragma unroll
        for (int j = 0; j < 16; ++j) {
            float c4[4] = {0.f, 0.f, 0.f, 0.f};
            u32 base = (8 * j + qr) * SF_STRIDE;
#pragma unroll
            for (int c = 0; c < 2; ++c) {
                u32 off = base + (16 * c + kq) * 2;
                u32 b0 = *(const u32*)(fb + off);
                u32 b1 = *(const u32*)(fb + off + 16);
                mma16816(c4, Ghi[c], b0, b1);
            }
            mrow0 = fmaxf(mrow0, fmaxf(c4[0], c4[1]));
            mrow1 = fmaxf(mrow1, fmaxf(c4[2], c4[3]));
        }
        __syncthreads();
    }
    mrow0 = fmaxf(mrow0, __shfl_xor_sync(0xffffffffu, mrow0, 1));
    mrow0 = fmaxf(mrow0, __shfl_xor_sync(0xffffffffu, mrow0, 2));
    mrow1 = fmaxf(mrow1, __shfl_xor_sync(0xffffffffu, mrow1, 1));
    mrow1 = fmaxf(mrow1, __shfl_xor_sync(0xffffffffu, mrow1, 2));
    const float mL0 = mrow0 * L2E, mL1 = mrow1 * L2E;

    // ================= Pass B =================
    float oa[32][4];
#pragma unroll
    for (int j = 0; j < 32; ++j) { oa[j][0] = oa[j][1] = oa[j][2] = oa[j][3] = 0.f; }
    float lacc[4] = {0.f, 0.f, 0.f, 0.f};

    {
#pragma unroll
        for (int i = 0; i < 4; i++) {
            int e = tid + 256 * i; int row = e >> 3, q = e & 7;
            cpa16(sFu[0] + row * SF_STRIDE + q * 16, fglob + row * 128 + q * 16);
        }
#pragma unroll
        for (int i = 0; i < 16; i++) {
            int e = tid + 256 * i; int row = e >> 4, q = e & 15;
            cpa16(sHu[0] + row * SH_STRIDE + q * 16, hglob + (size_t)row * 8192 + q * 16);
        }
        CP_COMMIT();
    }

#pragma unroll 1
    for (int kt = 0; kt < 32; ++kt) {
        if (kt < 31) {
            u32 sfb = sFu[(kt + 1) & 1], shb = sHu[(kt + 1) & 1];
            const char* gf = fglob + (size_t)(kt + 1) * 16384;
            const char* gh = hglob + (size_t)(kt + 1) * 256;
#pragma unroll
            for (int i = 0; i < 4; i++) {
                int e = tid + 256 * i; int row = e >> 3, q = e & 7;
                cpa16(sfb + row * SF_STRIDE + q * 16, gf + row * 128 + q * 16);
            }
#pragma unroll
            for (int i = 0; i < 16; i++) {
                int e = tid + 256 * i; int row = e >> 4, q = e & 15;
                cpa16(shb + row * SH_STRIDE + q * 16, gh + (size_t)row * 8192 + q * 16);
            }
            CP_COMMIT();
            CP_WAIT1();
        } else {
            CP_WAIT0();
        }
        __syncthreads();

        const char* fb = sFp[kt & 1];
        const char* hb = sHp[kt & 1];

#pragma unroll
        for (int kk = 0; kk < 8; ++kk) {
            float cA[4] = {0.f, 0.f, 0.f, 0.f};
            float cB[4] = {0.f, 0.f, 0.f, 0.f};
            u32 baseA = (16 * kk + qr) * SF_STRIDE;
            u32 baseB = baseA + 8 * SF_STRIDE;
#pragma unroll
            for (int c = 0; c < 2; ++c) {
                u32 off = (16 * c + kq) * 2;
                u32 ah0 = *(const u32*)(fb + baseA + off);
                u32 ah1 = *(const u32*)(fb + baseA + off + 16);
                u32 al0 = *(const u32*)(fb + baseA + off + 64);
                u32 al1 = *(const u32*)(fb + baseA + off + 80);
                u32 bh0 = *(const u32*)(fb + baseB + off);
                u32 bh1 = *(const u32*)(fb + baseB + off + 16);
                u32 bl0 = *(const u32*)(fb + baseB + off + 64);
                u32 bl1 = *(const u32*)(fb + baseB + off + 80);
                mma16816(cA, Ghi[c], ah0, ah1);
                mma16816(cB, Ghi[c], bh0, bh1);
                mma16816(cA, Glo[c], ah0, ah1);
                mma16816(cB, Glo[c], bh0, bh1);
                mma16816(cA, Ghi[c], al0, al1);
                mma16816(cB, Ghi[c], bl0, bl1);
            }
            u32 P[4];
            P[0] = f2h2u(exp2f(fmaf(cA[0], L2E, -mL0)), exp2f(fmaf(cA[1], L2E, -mL0)));
            P[1] = f2h2u(exp2f(fmaf(cA[2], L2E, -mL1)), exp2f(fmaf(cA[3], L2E, -mL1)));
            P[2] = f2h2u(exp2f(fmaf(cB[0], L2E, -mL0)), exp2f(fmaf(cB[1], L2E, -mL0)));
            P[3] = f2h2u(exp2f(fmaf(cB[2], L2E, -mL1)), exp2f(fmaf(cB[3], L2E, -mL1)));

            mma16816(lacc, P, ONES_H2, ONES_H2);

            u32 koff = (16 * kk + kq) * 2;
#pragma unroll
            for (int j2 = 0; j2 < 32; ++j2) {
                u32 a = (8 * j2 + qr) * SH_STRIDE + koff;
                mma16816(oa[j2], P, *(const u32*)(hb + a), *(const u32*)(hb + a + 16));
            }
        }
        __syncthreads();
    }

    // ---- epilogue: o = O / li ----
    {
        float inv0 = 1.0f / lacc[0];
        float inv1 = 1.0f / lacc[2];
        float* op = d_o + ((size_t)b * NN + q0 + 16 * w) * 256;
#pragma unroll
        for (int j2 = 0; j2 < 32; ++j2) {
            int cc = 8 * j2 + kq;
            *(float2*)(op + (size_t)qr * 256 + cc) =
                make_float2(oa[j2][0] * inv0, oa[j2][1] * inv0);
            *(float2*)(op + (size_t)(qr + 8) * 256 + cc) =
                make_float2(oa[j2][2] * inv1, oa[j2][3] * inv1);
        }
    }
}

// ---------------------------------------------------------------------------
extern "C" void kernel_launch(void* const* d_in, const int* in_sizes, int n_in,
                              void* d_out, int out_size)
{
    const float* x  = (const float*)d_in[0];
    const float* Wf = (const float*)d_in[1];
    const float* bf = (const float*)d_in[2];
    const float* Wg = (const float*)d_in[3];
    const float* bg = (const float*)d_in[4];
    const float* Wh = (const float*)d_in[5];
    const float* bh = (const float*)d_in[6];
    const float* Wv = (const float*)d_in[7];
    const float* bv = (const float*)d_in[8];
    float* out = (float*)d_out;

    cudaFuncSetAttribute(k_fgh,   cudaFuncAttributeMaxDynamicSharedMemorySize, FGH_SMEM);
    cudaFuncSetAttribute(k_vproj, cudaFuncAttributeMaxDynamicSharedMemorySize, VP_SMEM);
    cudaFuncSetAttribute(k_attn,  cudaFuncAttributeMaxDynamicSharedMemorySize, ATTN_SMEM);

    k_fgh<<<256, 320, FGH_SMEM>>>(x, Wh, bh, Wf, bf, Wg, bg);
    k_attn<<<dim3(32, 4), 256, ATTN_SMEM>>>();
    k_vproj<<<256, 256, VP_SMEM>>>(Wv, bv, x, out);
}